// round 1
// baseline (speedup 1.0000x reference)
#include <cuda_runtime.h>
#include <math.h>

#define B_IMG 8
#define N_PROP 1000
#define C_CLS 91
#define CM1 90
#define NCAND 90000      // N_PROP * CM1
#define K_TOP 2048
#define DET 36
#define D_FEAT 1024
#define BBOX_CLIP 4.135166556742356f

// ---------------- scratch (static device globals; no runtime alloc) ----------
__device__ unsigned long long g_list[B_IMG][NCAND];   // packed (score_bits<<32 | ~flat_idx)
__device__ int                g_M[B_IMG];             // valid candidate counts
__device__ unsigned long long g_top[B_IMG][K_TOP];    // sorted top candidates
__device__ int                g_K[B_IMG];             // effective K = min(M, 2048)
__device__ float4             g_boxes[B_IMG][K_TOP];  // decoded+clipped boxes of top cands
__device__ unsigned long long g_mask[B_IMG][K_TOP][K_TOP / 64]; // suppression bitmask
__device__ int                g_kept[B_IMG][DET];
__device__ int                g_kcount[B_IMG];

// ---------------- helpers ----------------------------------------------------
__device__ __forceinline__ float4 decode_clip(const float* __restrict__ reg,
                                              const float* __restrict__ props,
                                              int b, unsigned int flat,
                                              float wImg, float hImg) {
    int n = (int)(flat / CM1);
    int c = (int)(flat % CM1) + 1;            // skip background
    const float* p = props + ((size_t)b * N_PROP + n) * 4;
    float p0 = p[0], p1 = p[1], p2 = p[2], p3 = p[3];
    float wp = __fsub_rn(p2, p0);
    float hp = __fsub_rn(p3, p1);
    float cx = __fadd_rn(p0, __fmul_rn(0.5f, wp));
    float cy = __fadd_rn(p1, __fmul_rn(0.5f, hp));
    const float* r = reg + ((size_t)b * N_PROP + n) * (C_CLS * 4) + c * 4;
    float dx = __fdiv_rn(r[0], 10.0f);
    float dy = __fdiv_rn(r[1], 10.0f);
    float dw = fminf(__fdiv_rn(r[2], 5.0f), BBOX_CLIP);
    float dh = fminf(__fdiv_rn(r[3], 5.0f), BBOX_CLIP);
    float pcx = __fadd_rn(__fmul_rn(dx, wp), cx);
    float pcy = __fadd_rn(__fmul_rn(dy, hp), cy);
    float pw  = __fmul_rn(expf(dw), wp);
    float ph  = __fmul_rn(expf(dh), hp);
    float x1 = __fsub_rn(pcx, __fmul_rn(0.5f, pw));
    float y1 = __fsub_rn(pcy, __fmul_rn(0.5f, ph));
    float x2 = __fadd_rn(pcx, __fmul_rn(0.5f, pw));
    float y2 = __fadd_rn(pcy, __fmul_rn(0.5f, ph));
    x1 = fminf(fmaxf(x1, 0.0f), wImg);
    y1 = fminf(fmaxf(y1, 0.0f), hImg);
    x2 = fminf(fmaxf(x2, 0.0f), wImg);
    y2 = fminf(fmaxf(y2, 0.0f), hImg);
    return make_float4(x1, y1, x2, y2);
}

// ---------------- kernel 0: reset counters -----------------------------------
__global__ void reset_kernel() {
    int t = threadIdx.x;
    if (t < B_IMG) { g_M[t] = 0; g_kcount[t] = 0; }
}

// ---------------- kernel 1: softmax + filter + compact -----------------------
// one block per (b, n) proposal, 128 threads
__global__ void score_kernel(const float* __restrict__ logits,
                             const float* __restrict__ reg,
                             const float* __restrict__ props,
                             const int*   __restrict__ img_hw) {
    int bn = blockIdx.x;
    int b = bn / N_PROP;
    int n = bn % N_PROP;
    int t = threadIdx.x;
    __shared__ float red[128];

    const float* lrow = logits + (size_t)bn * C_CLS;
    float lv = (t < C_CLS) ? lrow[t] : -INFINITY;

    // max reduce
    red[t] = lv;
    __syncthreads();
    #pragma unroll
    for (int s = 64; s > 0; s >>= 1) {
        if (t < s) red[t] = fmaxf(red[t], red[t + s]);
        __syncthreads();
    }
    float m = red[0];
    __syncthreads();

    float e = (t < C_CLS) ? expf(__fsub_rn(lv, m)) : 0.0f;
    red[t] = e;
    __syncthreads();
    #pragma unroll
    for (int s = 64; s > 0; s >>= 1) {
        if (t < s) red[t] = __fadd_rn(red[t], red[t + s]);
        __syncthreads();
    }
    float ssum = red[0];

    if (t >= 1 && t < C_CLS) {
        float score = __fdiv_rn(e, ssum);
        if (score > 0.2f) {
            float hImg = (float)img_hw[b * 2 + 0];
            float wImg = (float)img_hw[b * 2 + 1];
            unsigned int flat = (unsigned int)(n * CM1 + (t - 1));
            float4 box = decode_clip(reg, props, b, flat, wImg, hImg);
            if (__fsub_rn(box.z, box.x) >= 0.01f && __fsub_rn(box.w, box.y) >= 0.01f) {
                int pos = atomicAdd(&g_M[b], 1);
                unsigned long long key =
                    ((unsigned long long)__float_as_uint(score) << 32) |
                    (unsigned long long)(unsigned int)(~flat);
                g_list[b][pos] = key;
            }
        }
    }
}

// ---------------- bitonic sort (descending) of 4096 u64 in smem --------------
__device__ void bitonic4096_desc(unsigned long long* buf) {
    const int n = 4096;
    for (int k = 2; k <= n; k <<= 1) {
        for (int j = k >> 1; j > 0; j >>= 1) {
            __syncthreads();
            for (int i = threadIdx.x; i < n; i += blockDim.x) {
                int ixj = i ^ j;
                if (ixj > i) {
                    unsigned long long a = buf[i], c = buf[ixj];
                    bool descSeg = ((i & k) == 0);
                    if (descSeg ? (a < c) : (a > c)) { buf[i] = c; buf[ixj] = a; }
                }
            }
        }
    }
    __syncthreads();
}

// ---------------- kernel 2: exact top-K select + box decode ------------------
// one block per image, 1024 threads
__global__ void select_kernel(const float* __restrict__ reg,
                              const float* __restrict__ props,
                              const int*   __restrict__ img_hw) {
    __shared__ unsigned long long buf[4096];
    int b = blockIdx.x;
    int tid = threadIdx.x;
    int M = g_M[b];

    int loaded = min(M, 4096);
    for (int i = tid; i < 4096; i += blockDim.x)
        buf[i] = (i < loaded) ? g_list[b][i] : 0ull;
    __syncthreads();
    bitonic4096_desc(buf);

    int consumed = loaded;
    while (consumed < M) {       // tournament: keep top 2048, refill bottom half
        int take = min(M - consumed, 2048);
        for (int s = tid; s < 2048; s += blockDim.x)
            buf[2048 + s] = (s < take) ? g_list[b][consumed + s] : 0ull;
        consumed += take;
        __syncthreads();
        bitonic4096_desc(buf);
    }

    int K = min(M, K_TOP);
    if (tid == 0) g_K[b] = K;
    float hImg = (float)img_hw[b * 2 + 0];
    float wImg = (float)img_hw[b * 2 + 1];
    for (int s = tid; s < K_TOP; s += blockDim.x) {
        unsigned long long key = buf[s];
        g_top[b][s] = key;
        float4 box = make_float4(0.f, 0.f, 0.f, 0.f);
        if (s < K) {
            unsigned int flat = ~(unsigned int)(key & 0xffffffffull);
            box = decode_clip(reg, props, b, flat, wImg, hImg);
        }
        g_boxes[b][s] = box;
    }
}

// ---------------- kernel 3: 64x64 suppression bitmask ------------------------
// grid (32 colblk, 32 rowblk, 8 img), 64 threads
__global__ void mask_kernel() {
    int cblk = blockIdx.x, rblk = blockIdx.y, b = blockIdx.z;
    int t = threadIdx.x;
    int i = rblk * 64 + t;
    unsigned long long word = 0ull;

    if (cblk >= rblk) {
        __shared__ float4 cb[64];
        __shared__ float  carea[64];
        int j0 = cblk * 64;
        float4 c4 = g_boxes[b][j0 + t];
        cb[t] = c4;
        carea[t] = __fmul_rn(__fsub_rn(c4.z, c4.x), __fsub_rn(c4.w, c4.y));
        __syncthreads();

        float4 a = g_boxes[b][i];
        float areaA = __fmul_rn(__fsub_rn(a.z, a.x), __fsub_rn(a.w, a.y));
        #pragma unroll 4
        for (int jj = 0; jj < 64; ++jj) {
            int j = j0 + jj;
            if (j <= i) continue;
            float4 c = cb[jj];
            float ltx = fmaxf(a.x, c.x), lty = fmaxf(a.y, c.y);
            float rbx = fminf(a.z, c.z), rby = fminf(a.w, c.w);
            float w = fmaxf(__fsub_rn(rbx, ltx), 0.0f);
            float h = fmaxf(__fsub_rn(rby, lty), 0.0f);
            float inter = __fmul_rn(w, h);
            if (inter > 0.0f) {
                float uni = __fsub_rn(__fadd_rn(areaA, carea[jj]), inter);
                float iou = __fdiv_rn(inter, uni);
                if (iou > 0.5f) word |= (1ull << jj);
            }
        }
    }
    g_mask[b][i][cblk] = word;
}

// ---------------- kernel 4: serial greedy scan (1 warp / image) --------------
__global__ void scan_kernel() {
    int b = blockIdx.x;
    int lane = threadIdx.x;           // 32 lanes, lane owns remv word `lane`
    int K = g_K[b];
    unsigned long long remv = 0ull;
    int kc = 0;
    for (int i = 0; i < K; ++i) {
        int w = i >> 6;
        unsigned long long rw = __shfl_sync(0xffffffffu, remv, w);
        if (!((rw >> (i & 63)) & 1ull)) {
            if (lane == 0) g_kept[b][kc] = i;
            kc++;
            if (kc >= DET) break;     // only first 36 kept matter
            remv |= g_mask[b][i][lane];
        }
    }
    if (lane == 0) g_kcount[b] = kc;
}

// ---------------- kernel 5: feature gather + zero pad ------------------------
// grid (36, 8), 256 threads (1024 floats = 256 float4)
__global__ void gather_kernel(const float* __restrict__ feats,
                              float* __restrict__ out) {
    int t = blockIdx.x;   // detection slot
    int b = blockIdx.y;
    int kc = g_kcount[b];
    float4* dst = (float4*)(out + ((size_t)b * DET + t) * D_FEAT);
    if (t < kc) {
        int slot = g_kept[b][t];
        unsigned int flat = ~(unsigned int)(g_top[b][slot] & 0xffffffffull);
        int pn = (int)(flat / CM1);
        const float4* src = (const float4*)(feats + ((size_t)b * N_PROP + pn) * D_FEAT);
        dst[threadIdx.x] = src[threadIdx.x];
    } else {
        dst[threadIdx.x] = make_float4(0.f, 0.f, 0.f, 0.f);
    }
}

// ---------------- launch ------------------------------------------------------
extern "C" void kernel_launch(void* const* d_in, const int* in_sizes, int n_in,
                              void* d_out, int out_size) {
    const float* logits = (const float*)d_in[0];   // [8,1000,91]
    const float* reg    = (const float*)d_in[1];   // [8,1000,364]
    const float* props  = (const float*)d_in[2];   // [8,1000,4]
    const float* feats  = (const float*)d_in[3];   // [8,1000,1024]
    const int*   imghw  = (const int*)d_in[4];     // [8,2]
    float* out = (float*)d_out;                    // [8,36,1024]

    reset_kernel<<<1, 32>>>();
    score_kernel<<<B_IMG * N_PROP, 128>>>(logits, reg, props, imghw);
    select_kernel<<<B_IMG, 1024>>>(reg, props, imghw);
    mask_kernel<<<dim3(K_TOP / 64, K_TOP / 64, B_IMG), 64>>>();
    scan_kernel<<<B_IMG, 32>>>();
    gather_kernel<<<dim3(DET, B_IMG), 256>>>(feats, out);
}

// round 2
// speedup vs baseline: 1.4628x; 1.4628x over previous
#include <cuda_runtime.h>
#include <math.h>

#define B_IMG 8
#define N_PROP 1000
#define C_CLS 91
#define CM1 90
#define NCAND 90000      // N_PROP * CM1
#define K_TOP 2048
#define DET 36
#define D_FEAT 1024
#define BBOX_CLIP 4.135166556742356f

// ---------------- scratch (static device globals; no runtime alloc) ----------
__device__ unsigned long long g_list[B_IMG][NCAND];   // packed (score_bits<<32 | ~flat_idx)
__device__ int                g_M[B_IMG];             // valid candidate counts

// ---------------- helpers ----------------------------------------------------
__device__ __forceinline__ float4 decode_clip(const float* __restrict__ reg,
                                              const float* __restrict__ props,
                                              int b, unsigned int flat,
                                              float wImg, float hImg) {
    int n = (int)(flat / CM1);
    int c = (int)(flat % CM1) + 1;            // skip background
    const float* p = props + ((size_t)b * N_PROP + n) * 4;
    float p0 = p[0], p1 = p[1], p2 = p[2], p3 = p[3];
    float wp = __fsub_rn(p2, p0);
    float hp = __fsub_rn(p3, p1);
    float cx = __fadd_rn(p0, __fmul_rn(0.5f, wp));
    float cy = __fadd_rn(p1, __fmul_rn(0.5f, hp));
    const float* r = reg + ((size_t)b * N_PROP + n) * (C_CLS * 4) + c * 4;
    float dx = __fdiv_rn(r[0], 10.0f);
    float dy = __fdiv_rn(r[1], 10.0f);
    float dw = fminf(__fdiv_rn(r[2], 5.0f), BBOX_CLIP);
    float dh = fminf(__fdiv_rn(r[3], 5.0f), BBOX_CLIP);
    float pcx = __fadd_rn(__fmul_rn(dx, wp), cx);
    float pcy = __fadd_rn(__fmul_rn(dy, hp), cy);
    float pw  = __fmul_rn(expf(dw), wp);
    float ph  = __fmul_rn(expf(dh), hp);
    float x1 = __fsub_rn(pcx, __fmul_rn(0.5f, pw));
    float y1 = __fsub_rn(pcy, __fmul_rn(0.5f, ph));
    float x2 = __fadd_rn(pcx, __fmul_rn(0.5f, pw));
    float y2 = __fadd_rn(pcy, __fmul_rn(0.5f, ph));
    x1 = fminf(fmaxf(x1, 0.0f), wImg);
    y1 = fminf(fmaxf(y1, 0.0f), hImg);
    x2 = fminf(fmaxf(x2, 0.0f), wImg);
    y2 = fminf(fmaxf(y2, 0.0f), hImg);
    return make_float4(x1, y1, x2, y2);
}

// ---------------- kernel 0: reset counters -----------------------------------
__global__ void reset_kernel() {
    int t = threadIdx.x;
    if (t < B_IMG) g_M[t] = 0;
}

// ---------------- kernel 1: softmax + filter + compact -----------------------
// one block per (b, n) proposal, 128 threads  (UNCHANGED: reduction shape fixes
// the rounding of score vs. the 0.2 threshold; rel_err was 0.0 with this shape)
__global__ void score_kernel(const float* __restrict__ logits,
                             const float* __restrict__ reg,
                             const float* __restrict__ props,
                             const int*   __restrict__ img_hw) {
    int bn = blockIdx.x;
    int b = bn / N_PROP;
    int n = bn % N_PROP;
    int t = threadIdx.x;
    __shared__ float red[128];

    const float* lrow = logits + (size_t)bn * C_CLS;
    float lv = (t < C_CLS) ? lrow[t] : -INFINITY;

    // max reduce
    red[t] = lv;
    __syncthreads();
    #pragma unroll
    for (int s = 64; s > 0; s >>= 1) {
        if (t < s) red[t] = fmaxf(red[t], red[t + s]);
        __syncthreads();
    }
    float m = red[0];
    __syncthreads();

    float e = (t < C_CLS) ? expf(__fsub_rn(lv, m)) : 0.0f;
    red[t] = e;
    __syncthreads();
    #pragma unroll
    for (int s = 64; s > 0; s >>= 1) {
        if (t < s) red[t] = __fadd_rn(red[t], red[t + s]);
        __syncthreads();
    }
    float ssum = red[0];

    if (t >= 1 && t < C_CLS) {
        float score = __fdiv_rn(e, ssum);
        if (score > 0.2f) {
            float hImg = (float)img_hw[b * 2 + 0];
            float wImg = (float)img_hw[b * 2 + 1];
            unsigned int flat = (unsigned int)(n * CM1 + (t - 1));
            float4 box = decode_clip(reg, props, b, flat, wImg, hImg);
            if (__fsub_rn(box.z, box.x) >= 0.01f && __fsub_rn(box.w, box.y) >= 0.01f) {
                int pos = atomicAdd(&g_M[b], 1);
                unsigned long long key =
                    ((unsigned long long)__float_as_uint(score) << 32) |
                    (unsigned long long)(unsigned int)(~flat);
                g_list[b][pos] = key;
            }
        }
    }
}

// ---------------- bitonic sort (descending), runtime power-of-two size -------
__device__ void bitonic_desc(unsigned long long* buf, int n) {
    for (int k = 2; k <= n; k <<= 1) {
        for (int j = k >> 1; j > 0; j >>= 1) {
            __syncthreads();
            for (int i = threadIdx.x; i < n; i += blockDim.x) {
                int ixj = i ^ j;
                if (ixj > i) {
                    unsigned long long a = buf[i], c = buf[ixj];
                    bool descSeg = ((i & k) == 0);
                    if (descSeg ? (a < c) : (a > c)) { buf[i] = c; buf[ixj] = a; }
                }
            }
        }
    }
    __syncthreads();
}

// ---------------- kernel 2: fused top-K sort + NMS + feature gather ----------
// one block per image, 1024 threads
__global__ __launch_bounds__(1024)
void fused_kernel(const float* __restrict__ reg,
                  const float* __restrict__ props,
                  const int*   __restrict__ img_hw,
                  const float* __restrict__ feats,
                  float* __restrict__ out) {
    __shared__ unsigned long long buf[4096];       // 32KB; aliased as sbox after sort
    __shared__ unsigned int  sidx[K_TOP];          // 8KB: flat candidate indices
    __shared__ unsigned char skeep[K_TOP];         // 2KB
    __shared__ int skept[DET];

    int b = blockIdx.x;
    int tid = threadIdx.x;
    int M = g_M[b];

    // ---- sort: runtime-size bitonic + tournament for M > 4096 ----
    int loaded = min(M, 4096);
    int n = 64;
    while (n < loaded) n <<= 1;
    for (int i = tid; i < n; i += blockDim.x)
        buf[i] = (i < loaded) ? g_list[b][i] : 0ull;
    __syncthreads();
    bitonic_desc(buf, n);

    int consumed = loaded;
    while (consumed < M) {       // keep top 2048, refill bottom half
        int take = min(M - consumed, 2048);
        for (int s = tid; s < 2048; s += blockDim.x)
            buf[2048 + s] = (s < take) ? g_list[b][consumed + s] : 0ull;
        consumed += take;
        __syncthreads();
        bitonic_desc(buf, 4096);
    }

    int K = min(M, K_TOP);

    // ---- extract flat indices (buf keys die after this) ----
    for (int s = tid; s < K; s += blockDim.x)
        sidx[s] = ~(unsigned int)(buf[s] & 0xffffffffull);
    __syncthreads();

    // ---- decode boxes into smem (aliases buf) ----
    float4* sbox = (float4*)buf;
    float hImg = (float)img_hw[b * 2 + 0];
    float wImg = (float)img_hw[b * 2 + 1];
    for (int s = tid; s < K; s += blockDim.x) {
        sbox[s] = decode_clip(reg, props, b, sidx[s], wImg, hImg);
        skeep[s] = 1;
    }
    __syncthreads();

    // ---- greedy NMS with on-the-fly IoU, early exit at DET kept ----
    int kc = 0;
    for (int i = 0; i < K && kc < DET; ++i) {
        if (skeep[i]) {
            if (tid == 0) skept[kc] = i;
            float4 a = sbox[i];
            float areaA = __fmul_rn(__fsub_rn(a.z, a.x), __fsub_rn(a.w, a.y));
            for (int j = i + 1 + tid; j < K; j += blockDim.x) {
                if (skeep[j]) {
                    float4 c = sbox[j];
                    float ltx = fmaxf(a.x, c.x), lty = fmaxf(a.y, c.y);
                    float rbx = fminf(a.z, c.z), rby = fminf(a.w, c.w);
                    float w = fmaxf(__fsub_rn(rbx, ltx), 0.0f);
                    float h = fmaxf(__fsub_rn(rby, lty), 0.0f);
                    float inter = __fmul_rn(w, h);
                    if (inter > 0.0f) {
                        float areaC = __fmul_rn(__fsub_rn(c.z, c.x), __fsub_rn(c.w, c.y));
                        float uni = __fsub_rn(__fadd_rn(areaA, areaC), inter);
                        if (__fdiv_rn(inter, uni) > 0.5f) skeep[j] = 0;
                    }
                }
            }
            kc++;
            __syncthreads();
        }
    }
    __syncthreads();

    // ---- feature gather: 36 rows x 256 float4, all threads ----
    for (int idx = tid; idx < DET * (D_FEAT / 4); idx += blockDim.x) {
        int t = idx >> 8;            // detection slot
        int q = idx & 255;           // float4 within row
        float4* dst = (float4*)(out + ((size_t)b * DET + t) * D_FEAT);
        if (t < kc) {
            int pn = (int)(sidx[skept[t]] / CM1);
            const float4* src = (const float4*)(feats + ((size_t)b * N_PROP + pn) * D_FEAT);
            dst[q] = src[q];
        } else {
            dst[q] = make_float4(0.f, 0.f, 0.f, 0.f);
        }
    }
}

// ---------------- launch ------------------------------------------------------
extern "C" void kernel_launch(void* const* d_in, const int* in_sizes, int n_in,
                              void* d_out, int out_size) {
    const float* logits = (const float*)d_in[0];   // [8,1000,91]
    const float* reg    = (const float*)d_in[1];   // [8,1000,364]
    const float* props  = (const float*)d_in[2];   // [8,1000,4]
    const float* feats  = (const float*)d_in[3];   // [8,1000,1024]
    const int*   imghw  = (const int*)d_in[4];     // [8,2]
    float* out = (float*)d_out;                    // [8,36,1024]

    reset_kernel<<<1, 32>>>();
    score_kernel<<<B_IMG * N_PROP, 128>>>(logits, reg, props, imghw);
    fused_kernel<<<B_IMG, 1024>>>(reg, props, imghw, feats, out);
}

// round 3
// speedup vs baseline: 1.5095x; 1.0319x over previous
#include <cuda_runtime.h>
#include <math.h>

#define B_IMG 8
#define N_PROP 1000
#define C_CLS 91
#define CM1 90
#define NCAND 90000      // N_PROP * CM1
#define K_TOP 2048
#define DET 36
#define D_FEAT 1024
#define BBOX_CLIP 4.135166556742356f

// ---------------- scratch (static device globals; zero-init at load) ---------
__device__ unsigned long long g_list[B_IMG][NCAND];   // packed (score_bits<<32 | ~flat_idx)
__device__ int                g_M[B_IMG];             // valid counts; reset by fused_kernel

// ---------------- helpers ----------------------------------------------------
__device__ __forceinline__ float4 decode_clip(const float* __restrict__ reg,
                                              const float* __restrict__ props,
                                              int b, unsigned int flat,
                                              float wImg, float hImg) {
    int n = (int)(flat / CM1);
    int c = (int)(flat % CM1) + 1;            // skip background
    const float* p = props + ((size_t)b * N_PROP + n) * 4;
    float p0 = p[0], p1 = p[1], p2 = p[2], p3 = p[3];
    float wp = __fsub_rn(p2, p0);
    float hp = __fsub_rn(p3, p1);
    float cx = __fadd_rn(p0, __fmul_rn(0.5f, wp));
    float cy = __fadd_rn(p1, __fmul_rn(0.5f, hp));
    const float* r = reg + ((size_t)b * N_PROP + n) * (C_CLS * 4) + c * 4;
    float dx = __fdiv_rn(r[0], 10.0f);
    float dy = __fdiv_rn(r[1], 10.0f);
    float dw = fminf(__fdiv_rn(r[2], 5.0f), BBOX_CLIP);
    float dh = fminf(__fdiv_rn(r[3], 5.0f), BBOX_CLIP);
    float pcx = __fadd_rn(__fmul_rn(dx, wp), cx);
    float pcy = __fadd_rn(__fmul_rn(dy, hp), cy);
    float pw  = __fmul_rn(expf(dw), wp);
    float ph  = __fmul_rn(expf(dh), hp);
    float x1 = __fsub_rn(pcx, __fmul_rn(0.5f, pw));
    float y1 = __fsub_rn(pcy, __fmul_rn(0.5f, ph));
    float x2 = __fadd_rn(pcx, __fmul_rn(0.5f, pw));
    float y2 = __fadd_rn(pcy, __fmul_rn(0.5f, ph));
    x1 = fminf(fmaxf(x1, 0.0f), wImg);
    y1 = fminf(fmaxf(y1, 0.0f), hImg);
    x2 = fminf(fmaxf(x2, 0.0f), wImg);
    y2 = fminf(fmaxf(y2, 0.0f), hImg);
    return make_float4(x1, y1, x2, y2);
}

// ---------------- kernel 1: softmax + filter + compact (warp per proposal) ---
// Reduction association is BIT-IDENTICAL to the previous 128-thread smem tree:
//   prologue (v0+v2)+v1 == tree steps s=64 (e(t)+e(t+64)) then s=32 (+e(t+32)+0),
//   xor-butterfly s=16..1 lane-0 result == tree red[0].
__global__ __launch_bounds__(256)
void score_kernel(const float* __restrict__ logits,
                  const float* __restrict__ reg,
                  const float* __restrict__ props,
                  const int*   __restrict__ img_hw) {
    int warp = (blockIdx.x * blockDim.x + threadIdx.x) >> 5;   // 0..7999
    int lane = threadIdx.x & 31;
    int b = warp / N_PROP;
    int n = warp % N_PROP;

    const float* lrow = logits + (size_t)warp * C_CLS;
    float l0 = lrow[lane];
    float l1 = (lane + 32 < C_CLS) ? lrow[lane + 32] : -INFINITY;
    float l2 = (lane + 64 < C_CLS) ? lrow[lane + 64] : -INFINITY;

    // max (exact, order-free)
    float m = fmaxf(fmaxf(l0, l2), l1);
    #pragma unroll
    for (int s = 16; s > 0; s >>= 1)
        m = fmaxf(m, __shfl_xor_sync(0xffffffffu, m, s));
    m = __shfl_sync(0xffffffffu, m, 0);

    float e0 = expf(__fsub_rn(l0, m));
    float e1 = expf(__fsub_rn(l1, m));   // expf(-inf)=+0 matches old zero-pad
    float e2 = expf(__fsub_rn(l2, m));

    float v = __fadd_rn(__fadd_rn(e0, e2), e1);
    #pragma unroll
    for (int s = 16; s > 0; s >>= 1)
        v = __fadd_rn(v, __shfl_xor_sync(0xffffffffu, v, s));
    float ssum = __shfl_sync(0xffffffffu, v, 0);

    float hImg = (float)img_hw[b * 2 + 0];
    float wImg = (float)img_hw[b * 2 + 1];

    float ecls[3] = {e0, e1, e2};
    #pragma unroll
    for (int k = 0; k < 3; ++k) {
        int c = lane + 32 * k;
        if (c >= 1 && c < C_CLS) {
            float score = __fdiv_rn(ecls[k], ssum);
            if (score > 0.2f) {
                unsigned int flat = (unsigned int)(n * CM1 + (c - 1));
                float4 box = decode_clip(reg, props, b, flat, wImg, hImg);
                if (__fsub_rn(box.z, box.x) >= 0.01f && __fsub_rn(box.w, box.y) >= 0.01f) {
                    int pos = atomicAdd(&g_M[b], 1);
                    unsigned long long key =
                        ((unsigned long long)__float_as_uint(score) << 32) |
                        (unsigned long long)(unsigned int)(~flat);
                    g_list[b][pos] = key;
                }
            }
        }
    }
}

// ---------------- bitonic sort (descending), runtime power-of-two size -------
__device__ void bitonic_desc(unsigned long long* buf, int n) {
    for (int k = 2; k <= n; k <<= 1) {
        for (int j = k >> 1; j > 0; j >>= 1) {
            __syncthreads();
            for (int i = threadIdx.x; i < n; i += blockDim.x) {
                int ixj = i ^ j;
                if (ixj > i) {
                    unsigned long long a = buf[i], c = buf[ixj];
                    bool descSeg = ((i & k) == 0);
                    if (descSeg ? (a < c) : (a > c)) { buf[i] = c; buf[ixj] = a; }
                }
            }
        }
    }
    __syncthreads();
}

// ---------------- kernel 2: fused top-K sort + NMS + feature gather ----------
// one block per image, 1024 threads
__global__ __launch_bounds__(1024)
void fused_kernel(const float* __restrict__ reg,
                  const float* __restrict__ props,
                  const int*   __restrict__ img_hw,
                  const float* __restrict__ feats,
                  float* __restrict__ out) {
    __shared__ unsigned long long buf[4096];       // 32KB; aliased as sbox after sort
    __shared__ unsigned int  sidx[K_TOP];          // 8KB: flat candidate indices
    __shared__ unsigned char skeep[K_TOP];         // 2KB
    __shared__ int skept[DET];

    int b = blockIdx.x;
    int tid = threadIdx.x;
    int M = g_M[b];

    // ---- sort: runtime-size bitonic + tournament for M > 4096 ----
    int loaded = min(M, 4096);
    int n = 64;
    while (n < loaded) n <<= 1;
    for (int i = tid; i < n; i += blockDim.x)
        buf[i] = (i < loaded) ? g_list[b][i] : 0ull;
    __syncthreads();
    bitonic_desc(buf, n);

    int consumed = loaded;
    while (consumed < M) {       // keep top 2048, refill bottom half
        int take = min(M - consumed, 2048);
        for (int s = tid; s < 2048; s += blockDim.x)
            buf[2048 + s] = (s < take) ? g_list[b][consumed + s] : 0ull;
        consumed += take;
        __syncthreads();
        bitonic_desc(buf, 4096);
    }

    int K = min(M, K_TOP);

    // ---- extract flat indices (buf keys die after this) ----
    for (int s = tid; s < K; s += blockDim.x)
        sidx[s] = ~(unsigned int)(buf[s] & 0xffffffffull);
    __syncthreads();

    // ---- decode boxes into smem (aliases buf) ----
    float4* sbox = (float4*)buf;
    float hImg = (float)img_hw[b * 2 + 0];
    float wImg = (float)img_hw[b * 2 + 1];
    for (int s = tid; s < K; s += blockDim.x) {
        sbox[s] = decode_clip(reg, props, b, sidx[s], wImg, hImg);
        skeep[s] = 1;
    }
    __syncthreads();

    // ---- greedy NMS with on-the-fly IoU, early exit at DET kept ----
    int kc = 0;
    for (int i = 0; i < K && kc < DET; ++i) {
        if (skeep[i]) {
            if (tid == 0) skept[kc] = i;
            float4 a = sbox[i];
            float areaA = __fmul_rn(__fsub_rn(a.z, a.x), __fsub_rn(a.w, a.y));
            for (int j = i + 1 + tid; j < K; j += blockDim.x) {
                if (skeep[j]) {
                    float4 c = sbox[j];
                    float ltx = fmaxf(a.x, c.x), lty = fmaxf(a.y, c.y);
                    float rbx = fminf(a.z, c.z), rby = fminf(a.w, c.w);
                    float w = fmaxf(__fsub_rn(rbx, ltx), 0.0f);
                    float h = fmaxf(__fsub_rn(rby, lty), 0.0f);
                    float inter = __fmul_rn(w, h);
                    if (inter > 0.0f) {
                        float areaC = __fmul_rn(__fsub_rn(c.z, c.x), __fsub_rn(c.w, c.y));
                        float uni = __fsub_rn(__fadd_rn(areaA, areaC), inter);
                        if (__fdiv_rn(inter, uni) > 0.5f) skeep[j] = 0;
                    }
                }
            }
            kc++;
            __syncthreads();
        }
    }
    __syncthreads();

    // ---- feature gather: 36 rows x 256 float4, all threads ----
    for (int idx = tid; idx < DET * (D_FEAT / 4); idx += blockDim.x) {
        int t = idx >> 8;            // detection slot
        int q = idx & 255;           // float4 within row
        float4* dst = (float4*)(out + ((size_t)b * DET + t) * D_FEAT);
        if (t < kc) {
            int pn = (int)(sidx[skept[t]] / CM1);
            const float4* src = (const float4*)(feats + ((size_t)b * N_PROP + pn) * D_FEAT);
            dst[q] = src[q];
        } else {
            dst[q] = make_float4(0.f, 0.f, 0.f, 0.f);
        }
    }

    // ---- self-reset for next graph replay (only this block reads g_M[b]) ----
    if (tid == 0) g_M[b] = 0;
}

// ---------------- launch ------------------------------------------------------
extern "C" void kernel_launch(void* const* d_in, const int* in_sizes, int n_in,
                              void* d_out, int out_size) {
    const float* logits = (const float*)d_in[0];   // [8,1000,91]
    const float* reg    = (const float*)d_in[1];   // [8,1000,364]
    const float* props  = (const float*)d_in[2];   // [8,1000,4]
    const float* feats  = (const float*)d_in[3];   // [8,1000,1024]
    const int*   imghw  = (const int*)d_in[4];     // [8,2]
    float* out = (float*)d_out;                    // [8,36,1024]

    score_kernel<<<B_IMG * N_PROP / 8, 256>>>(logits, reg, props, imghw);
    fused_kernel<<<B_IMG, 1024>>>(reg, props, imghw, feats, out);
}